// round 1
// baseline (speedup 1.0000x reference)
#include <cuda_runtime.h>
#include <cstdint>

// Problem constants (shapes fixed by the dataset)
#define MAXN   200000
#define MAXE   500000
#define F_IN_  165
#define HID_   256
#define KTOT   330      // 165 (agg) + 165 (root)
#define APAD   168      // padded agg row stride (16B-friendly)

// ---------------- scratch (static device allocations) ----------------
__device__ __align__(16) float g_agg[(size_t)MAXN * APAD];   // ~134 MB
__device__ __align__(16) float g_h  [(size_t)MAXN * HID_];   // ~205 MB
__device__ __align__(16) float g_deg [MAXN];                 // deg, then 1/max(deg,1)
__device__ __align__(16) float g_t   [MAXN * 2];             // h @ w2_l
__device__ __align__(16) float g_rr  [MAXN * 2];             // h @ w2_r
__device__ __align__(16) float g_agg2[MAXN * 2];
__device__ int g_ei[2 * MAXE];                               // canonical int32 edge index
__device__ int g_is64;

// ---------------- edge-index dtype detection + canonicalization ----------------
// If edge_index is int64 (values < 2^31), the int32 view has all-zero odd words.
__global__ void detect_kernel(const void* ei, int twoE) {
    const int* p = (const int*)ei;
    int nz = 0;
    for (int i = threadIdx.x; i < 256; i += 32) {
        if (2 * i + 1 < twoE) nz += (p[2 * i + 1] != 0);
    }
    #pragma unroll
    for (int o = 16; o; o >>= 1) nz += __shfl_xor_sync(0xffffffffu, nz, o);
    if (threadIdx.x == 0) g_is64 = (nz == 0) ? 1 : 0;
}

__global__ void convert_ei_kernel(const void* ei, int twoE) {
    int is64 = g_is64;
    const long long* p64 = (const long long*)ei;
    const int*       p32 = (const int*)ei;
    for (int i = blockIdx.x * blockDim.x + threadIdx.x; i < twoE;
         i += gridDim.x * blockDim.x) {
        g_ei[i] = is64 ? (int)p64[i] : p32[i];
    }
}

// ---------------- zero scratch that is accumulated into ----------------
__global__ void zero_all_kernel(int N) {
    size_t stride = (size_t)gridDim.x * blockDim.x;
    size_t tid = (size_t)blockIdx.x * blockDim.x + threadIdx.x;
    float4 z = make_float4(0.f, 0.f, 0.f, 0.f);
    size_t n4 = (size_t)N * (APAD / 4);
    float4* a4 = (float4*)g_agg;
    for (size_t i = tid; i < n4; i += stride) a4[i] = z;
    for (size_t i = tid; i < (size_t)N; i += stride) g_deg[i] = 0.f;
    for (size_t i = tid; i < (size_t)2 * N; i += stride) g_agg2[i] = 0.f;
}

// ---------------- layer-1 scatter: warp per edge ----------------
__global__ void scatter1_kernel(const float* __restrict__ x, int E) {
    int warp = (blockIdx.x * blockDim.x + threadIdx.x) >> 5;
    int lane = threadIdx.x & 31;
    if (warp >= E) return;
    int s = g_ei[warp];
    int d = g_ei[E + warp];
    const float* xs = x + (size_t)s * F_IN_;
    float* ad = g_agg + (size_t)d * APAD;
    for (int f = lane; f < F_IN_; f += 32) atomicAdd(ad + f, xs[f]);
    if (lane == 0) atomicAdd(&g_deg[d], 1.0f);
}

__global__ void invd_kernel(int N) {
    int i = blockIdx.x * blockDim.x + threadIdx.x;
    if (i < N) g_deg[i] = 1.0f / fmaxf(g_deg[i], 1.0f);
}

// ---------------- layer-1 GEMM: h = relu([agg*invd | x] @ [w1_l; w1_r] + b1) ----------------
#define BM 64
#define BN 256
#define BK 32

__global__ __launch_bounds__(256) void gemm1_kernel(
    const float* __restrict__ x, const float* __restrict__ w1l,
    const float* __restrict__ w1r, const float* __restrict__ b1, int nrows)
{
    __shared__ float As[BK][BM];
    __shared__ float Bs[BK][BN];
    const int bm  = blockIdx.x * BM;
    const int tid = threadIdx.x;
    const int tr  = tid >> 5;             // 0..7  (row group, 8 rows each)
    const int tc  = tid & 31;             // 0..31 (col group, 8 cols each)
    const int ar  = tid & 63;             // A-load row within tile
    const int akb = (tid >> 6) << 3;      // A-load k base: 0,8,16,24
    const int grow = bm + ar;
    const bool rvalid = grow < nrows;
    float invd = 0.f;
    const float* arow = g_agg;            // dummy-safe
    const float* xrow = x;
    if (rvalid) {
        invd = g_deg[grow];
        arow = g_agg + (size_t)grow * APAD;
        xrow = x + (size_t)grow * F_IN_;
    }

    float acc[8][8];
    #pragma unroll
    for (int i = 0; i < 8; i++)
        #pragma unroll
        for (int j = 0; j < 8; j++) acc[i][j] = 0.f;

    for (int k0 = 0; k0 < KTOT; k0 += BK) {
        // A tile: 64 rows x 32 k, 8 consecutive k per thread (32B/sector-friendly)
        #pragma unroll
        for (int j = 0; j < 8; j++) {
            int k = k0 + akb + j;
            float v = 0.f;
            if (rvalid) {
                if (k < F_IN_)      v = arow[k] * invd;
                else if (k < KTOT)  v = xrow[k - F_IN_];
            }
            As[akb + j][ar] = v;
        }
        // B tile: 32 k x 256 cols, col = tid (coalesced)
        #pragma unroll
        for (int i = 0; i < BK; i++) {
            int k = k0 + i;
            float v = 0.f;
            if (k < F_IN_)      v = w1l[k * HID_ + tid];
            else if (k < KTOT)  v = w1r[(k - F_IN_) * HID_ + tid];
            Bs[i][tid] = v;
        }
        __syncthreads();
        #pragma unroll
        for (int kk = 0; kk < BK; kk++) {
            float4 a0 = *(const float4*)&As[kk][tr * 8];
            float4 a1 = *(const float4*)&As[kk][tr * 8 + 4];
            float4 b0 = *(const float4*)&Bs[kk][tc * 8];
            float4 b1v = *(const float4*)&Bs[kk][tc * 8 + 4];
            float a[8] = {a0.x, a0.y, a0.z, a0.w, a1.x, a1.y, a1.z, a1.w};
            float b[8] = {b0.x, b0.y, b0.z, b0.w, b1v.x, b1v.y, b1v.z, b1v.w};
            #pragma unroll
            for (int i = 0; i < 8; i++)
                #pragma unroll
                for (int j = 0; j < 8; j++) acc[i][j] += a[i] * b[j];
        }
        __syncthreads();
    }

    // epilogue: + b1, relu, store h
    float bb[8];
    #pragma unroll
    for (int j = 0; j < 8; j++) bb[j] = __ldg(&b1[tc * 8 + j]);
    #pragma unroll
    for (int i = 0; i < 8; i++) {
        int r = bm + tr * 8 + i;
        if (r < nrows) {
            float4 o0, o1;
            o0.x = fmaxf(acc[i][0] + bb[0], 0.f);
            o0.y = fmaxf(acc[i][1] + bb[1], 0.f);
            o0.z = fmaxf(acc[i][2] + bb[2], 0.f);
            o0.w = fmaxf(acc[i][3] + bb[3], 0.f);
            o1.x = fmaxf(acc[i][4] + bb[4], 0.f);
            o1.y = fmaxf(acc[i][5] + bb[5], 0.f);
            o1.z = fmaxf(acc[i][6] + bb[6], 0.f);
            o1.w = fmaxf(acc[i][7] + bb[7], 0.f);
            float* hp = g_h + (size_t)r * HID_ + tc * 8;
            *(float4*)hp       = o0;
            *(float4*)(hp + 4) = o1;
        }
    }
}

// ---------------- layer-2 projections (transform BEFORE aggregation) ----------------
// t = h @ w2_l, rr = h @ w2_r   (both [N, 2]) — warp per row
__global__ void proj2_kernel(const float* __restrict__ w2l,
                             const float* __restrict__ w2r, int N) {
    __shared__ float wl[HID_ * 2];
    __shared__ float wr[HID_ * 2];
    for (int i = threadIdx.x; i < HID_ * 2; i += blockDim.x) {
        wl[i] = w2l[i];
        wr[i] = w2r[i];
    }
    __syncthreads();
    int lane = threadIdx.x & 31;
    int row = blockIdx.x * (blockDim.x >> 5) + (threadIdx.x >> 5);
    if (row >= N) return;
    const float* hrow = g_h + (size_t)row * HID_;
    float t0 = 0.f, t1 = 0.f, r0 = 0.f, r1 = 0.f;
    #pragma unroll
    for (int j = 0; j < 8; j++) {
        int k = lane + 32 * j;
        float hv = hrow[k];
        t0 += hv * wl[k * 2];
        t1 += hv * wl[k * 2 + 1];
        r0 += hv * wr[k * 2];
        r1 += hv * wr[k * 2 + 1];
    }
    #pragma unroll
    for (int o = 16; o; o >>= 1) {
        t0 += __shfl_xor_sync(0xffffffffu, t0, o);
        t1 += __shfl_xor_sync(0xffffffffu, t1, o);
        r0 += __shfl_xor_sync(0xffffffffu, r0, o);
        r1 += __shfl_xor_sync(0xffffffffu, r1, o);
    }
    if (lane == 0) {
        g_t[row * 2]      = t0;
        g_t[row * 2 + 1]  = t1;
        g_rr[row * 2]     = r0;
        g_rr[row * 2 + 1] = r1;
    }
}

// layer-2 scatter: thread per edge, only 2 floats (transform-first rewrite)
__global__ void scatter2_kernel(int E) {
    int e = blockIdx.x * blockDim.x + threadIdx.x;
    if (e >= E) return;
    int s = g_ei[e];
    int d = g_ei[E + e];
    float2 v = *(const float2*)&g_t[s * 2];
    atomicAdd(&g_agg2[d * 2],     v.x);
    atomicAdd(&g_agg2[d * 2 + 1], v.y);
}

__global__ void finalize_kernel(float* __restrict__ out,
                                const float* __restrict__ b2, int N) {
    int i = blockIdx.x * blockDim.x + threadIdx.x;
    if (i >= N) return;
    float inv = g_deg[i];
    float2 a = *(const float2*)&g_agg2[2 * i];
    float2 r = *(const float2*)&g_rr[2 * i];
    float2 o;
    o.x = a.x * inv + r.x + __ldg(&b2[0]);
    o.y = a.y * inv + r.y + __ldg(&b2[1]);
    *(float2*)&out[2 * i] = o;
}

// ---------------- edge_index passthrough into output ----------------
__global__ void ei_out_f32_kernel(float* out, int twoE) {
    int i = blockIdx.x * blockDim.x + threadIdx.x;
    if (i < twoE) out[i] = (float)g_ei[i];
}
__global__ void ei_out_i64_kernel(long long* out, int twoE) {
    int i = blockIdx.x * blockDim.x + threadIdx.x;
    if (i < twoE) out[i] = (long long)g_ei[i];
}

// ---------------- launch ----------------
extern "C" void kernel_launch(void* const* d_in, const int* in_sizes, int n_in,
                              void* d_out, int out_size) {
    const float* x   = (const float*)d_in[0];
    const void*  ei  = d_in[1];
    const float* w1l = (const float*)d_in[2];
    const float* w1r = (const float*)d_in[3];
    const float* b1  = (const float*)d_in[4];
    const float* w2l = (const float*)d_in[5];
    const float* w2r = (const float*)d_in[6];
    const float* b2  = (const float*)d_in[7];

    int N = in_sizes[0] / F_IN_;
    int twoE = in_sizes[1];
    int E = twoE / 2;
    float* out = (float*)d_out;

    detect_kernel<<<1, 32>>>(ei, twoE);
    convert_ei_kernel<<<1024, 256>>>(ei, twoE);
    zero_all_kernel<<<4096, 256>>>(N);
    scatter1_kernel<<<(E * 32 + 255) / 256, 256>>>(x, E);
    invd_kernel<<<(N + 255) / 256, 256>>>(N);
    gemm1_kernel<<<(N + BM - 1) / BM, 256>>>(x, w1l, w1r, b1, N);
    proj2_kernel<<<(N + 7) / 8, 256>>>(w2l, w2r, N);
    scatter2_kernel<<<(E + 255) / 256, 256>>>(E);
    finalize_kernel<<<(N + 255) / 256, 256>>>(out, b2, N);

    // Append edge_index if the output buffer expects it.
    long long rem = (long long)out_size - (long long)2 * N;
    if (rem >= (long long)twoE) {
        if (rem >= 2LL * twoE) {
            // raw int64 layout occupying 2 float slots per value
            ei_out_i64_kernel<<<(twoE + 255) / 256, 256>>>(
                (long long*)(out + (size_t)2 * N), twoE);
        } else {
            // cast to output dtype (float32); node ids < 2^24 so exact
            ei_out_f32_kernel<<<(twoE + 255) / 256, 256>>>(
                out + (size_t)2 * N, twoE);
        }
    }
}

// round 3
// speedup vs baseline: 3.1076x; 3.1076x over previous
#include <cuda_runtime.h>
#include <cuda_bf16.h>
#include <cstdint>

// ---------------- problem constants ----------------
#define MAXN   200000
#define MAXE   500000
#define F_IN_  165
#define HID_   256
#define KTOT   330
#define APAD   168            // padded fp32 agg row stride
#define KPAD   384            // padded K (12 chunks of 32)
#define BK     32
#define NITER  (KPAD / BK)    // 12

// ---------------- device scratch ----------------
__device__ __align__(16) float g_agg[(size_t)MAXN * APAD];
__device__ float g_deg[MAXN];
__device__ __align__(16) float g_t  [MAXN * 2];
__device__ __align__(16) float g_rr [MAXN * 2];
__device__ __align__(16) float g_agg2[MAXN * 2];
__device__ __align__(16) __nv_bfloat16 g_Ahi[(size_t)MAXN * KPAD];
__device__ __align__(16) __nv_bfloat16 g_Alo[(size_t)MAXN * KPAD];
__device__ __align__(16) __nv_bfloat16 g_Bhi[HID_ * KPAD];
__device__ __align__(16) __nv_bfloat16 g_Blo[HID_ * KPAD];
__device__ int g_ei[2 * MAXE];
__device__ int g_is64;

// ---------------- PTX helpers (base-ISA only; tcgen05 is sm_103a-gated) ----------------
__device__ __forceinline__ uint32_t smem_u32(const void* p) {
    uint32_t a;
    asm("{ .reg .u64 t; cvta.to.shared.u64 t, %1; cvt.u32.u64 %0, t; }" : "=r"(a) : "l"(p));
    return a;
}
__device__ __forceinline__ void ldsm4(uint32_t& r0, uint32_t& r1, uint32_t& r2, uint32_t& r3,
                                      uint32_t addr) {
    asm volatile("ldmatrix.sync.aligned.m8n8.x4.shared.b16 {%0,%1,%2,%3}, [%4];"
                 : "=r"(r0), "=r"(r1), "=r"(r2), "=r"(r3) : "r"(addr));
}
#define MMA16816(c, a0, a1, a2, a3, b0, b1)                                            \
    asm volatile(                                                                      \
        "mma.sync.aligned.m16n8k16.row.col.f32.bf16.bf16.f32 "                         \
        "{%0,%1,%2,%3}, {%4,%5,%6,%7}, {%8,%9}, {%0,%1,%2,%3};"                        \
        : "+f"((c)[0]), "+f"((c)[1]), "+f"((c)[2]), "+f"((c)[3])                       \
        : "r"(a0), "r"(a1), "r"(a2), "r"(a3), "r"(b0), "r"(b1))
#define CP16(dst, src, pred)                                                           \
    asm volatile("cp.async.cg.shared.global [%0], [%1], 16, %2;"                       \
                 :: "r"(dst), "l"(src), "r"((pred) ? 16 : 0) : "memory")
#define CP_COMMIT() asm volatile("cp.async.commit_group;" ::: "memory")
#define CP_WAIT0()  asm volatile("cp.async.wait_group 0;" ::: "memory")

// ---------------- edge index canon ----------------
__global__ void detect_kernel(const void* ei, int twoE) {
    const int* p = (const int*)ei;
    int nz = 0;
    for (int i = threadIdx.x; i < 256; i += 32)
        if (2 * i + 1 < twoE) nz += (p[2 * i + 1] != 0);
    #pragma unroll
    for (int o = 16; o; o >>= 1) nz += __shfl_xor_sync(0xffffffffu, nz, o);
    if (threadIdx.x == 0) g_is64 = (nz == 0) ? 1 : 0;
}
__global__ void convert_ei_kernel(const void* ei, int twoE) {
    int is64 = g_is64;
    const long long* p64 = (const long long*)ei;
    const int* p32 = (const int*)ei;
    for (int i = blockIdx.x * blockDim.x + threadIdx.x; i < twoE; i += gridDim.x * blockDim.x)
        g_ei[i] = is64 ? (int)p64[i] : p32[i];
}

// ---------------- zero ----------------
__global__ void zero_all_kernel(int N) {
    size_t stride = (size_t)gridDim.x * blockDim.x;
    size_t tid = (size_t)blockIdx.x * blockDim.x + threadIdx.x;
    float4 z = make_float4(0.f, 0.f, 0.f, 0.f);
    size_t n4 = (size_t)N * (APAD / 4);
    float4* a4 = (float4*)g_agg;
    for (size_t i = tid; i < n4; i += stride) a4[i] = z;
    for (size_t i = tid; i < (size_t)N; i += stride) g_deg[i] = 0.f;
    float4* t4 = (float4*)g_t;
    float4* r4 = (float4*)g_rr;
    float4* a2 = (float4*)g_agg2;
    for (size_t i = tid; i < (size_t)N / 2; i += stride) { t4[i] = z; r4[i] = z; a2[i] = z; }
}

// ---------------- layer-1 scatter (vector red) ----------------
__global__ void scatter1_kernel(const float* __restrict__ x, int E) {
    int warp = (blockIdx.x * blockDim.x + threadIdx.x) >> 5;
    int lane = threadIdx.x & 31;
    if (warp >= E) return;
    int s = g_ei[warp];
    int d = g_ei[E + warp];
    const float* xs = x + (size_t)s * F_IN_;
    float* ad = g_agg + (size_t)d * APAD;
    for (int g = lane; g < 42; g += 32) {
        int f = g * 4;
        float a0 = xs[f];
        float a1 = (f + 1 < F_IN_) ? xs[f + 1] : 0.f;
        float a2 = (f + 2 < F_IN_) ? xs[f + 2] : 0.f;
        float a3 = (f + 3 < F_IN_) ? xs[f + 3] : 0.f;
        asm volatile("red.global.add.v4.f32 [%0], {%1, %2, %3, %4};"
                     :: "l"(ad + f), "f"(a0), "f"(a1), "f"(a2), "f"(a3) : "memory");
    }
    if (lane == 0) atomicAdd(&g_deg[d], 1.0f);
}

__global__ void invd_kernel(int N) {
    int i = blockIdx.x * blockDim.x + threadIdx.x;
    if (i < N) g_deg[i] = 1.0f / fmaxf(g_deg[i], 1.0f);
}

// ---------------- bf16 hi/lo split prep ----------------
__global__ void prep_A_kernel(const float* __restrict__ x, int N) {
    int u = blockIdx.x * blockDim.x + threadIdx.x;
    int total = N * (KPAD / 8);
    if (u >= total) return;
    int row = u / (KPAD / 8);
    int kb = (u % (KPAD / 8)) * 8;
    float inv = g_deg[row];
    __align__(16) __nv_bfloat16 hi[8], lo[8];
    #pragma unroll
    for (int j = 0; j < 8; j++) {
        int k = kb + j;
        float v = 0.f;
        if (k < F_IN_)      v = g_agg[(size_t)row * APAD + k] * inv;
        else if (k < KTOT)  v = x[(size_t)row * F_IN_ + (k - F_IN_)];
        __nv_bfloat16 h = __float2bfloat16(v);
        hi[j] = h;
        lo[j] = __float2bfloat16(v - __bfloat162float(h));
    }
    *(uint4*)(g_Ahi + (size_t)row * KPAD + kb) = *(const uint4*)hi;
    *(uint4*)(g_Alo + (size_t)row * KPAD + kb) = *(const uint4*)lo;
}

__global__ void prep_B_kernel(const float* __restrict__ w1l, const float* __restrict__ w1r) {
    int u = blockIdx.x * blockDim.x + threadIdx.x;
    if (u >= HID_ * (KPAD / 8)) return;
    int n = u / (KPAD / 8);
    int kb = (u % (KPAD / 8)) * 8;
    __align__(16) __nv_bfloat16 hi[8], lo[8];
    #pragma unroll
    for (int j = 0; j < 8; j++) {
        int k = kb + j;
        float v = 0.f;
        if (k < F_IN_)      v = w1l[k * HID_ + n];
        else if (k < KTOT)  v = w1r[(k - F_IN_) * HID_ + n];
        __nv_bfloat16 h = __float2bfloat16(v);
        hi[j] = h;
        lo[j] = __float2bfloat16(v - __bfloat162float(h));
    }
    *(uint4*)(g_Bhi + (size_t)n * KPAD + kb) = *(const uint4*)hi;
    *(uint4*)(g_Blo + (size_t)n * KPAD + kb) = *(const uint4*)lo;
}

// ---------------- mma.sync GEMM + fused layer-2 projection ----------------
// h = relu([agg*invd | x] @ W1 + b1) via bf16x3 (hi*hi + hi*lo + lo*hi).
// Fused epilogue: partial t = h@w2_l, rr = h@w2_r red-added per row (h never stored).
//
// Block tile 128(M) x 128(N), 8 warps as 2(M) x 4(N), warp tile 64x32.
// smem tiles: stride 80B per 32-k row (bank-friendly for ldmatrix).
#define ROWB   80
#define T_A    (128 * ROWB)         // 10240 per matrix
#define STAGE  (4 * T_A)            // Ahi, Alo, Bhi, Blo = 40960
#define OFF_AL T_A
#define OFF_BH (2 * T_A)
#define OFF_BL (3 * T_A)
#define SM_W2  (2 * STAGE)          // 81920
#define SMEM_DYN (SM_W2 + 512 + 1024 + 1024)

__global__ __launch_bounds__(256) void gemm_tc_kernel(
    const float* __restrict__ b1, const float* __restrict__ w2l,
    const float* __restrict__ w2r, int N)
{
    extern __shared__ __align__(16) char sm[];
    uint32_t sb = smem_u32(sm);
    float* b1s  = (float*)(sm + SM_W2);
    float* w2ls = (float*)(sm + SM_W2 + 512);
    float* w2rs = (float*)(sm + SM_W2 + 512 + 1024);

    const int tid  = threadIdx.x;
    const int wid  = tid >> 5;
    const int lane = tid & 31;
    const int wm   = wid >> 2;          // 0..1
    const int wn   = wid & 3;           // 0..3
    const size_t rowbase = (size_t)blockIdx.x * 128;
    const int    nb      = blockIdx.y * 128;

    // stage-local epilogue constants
    for (int i = tid; i < 128; i += 256) b1s[i] = b1[nb + i];
    for (int i = tid; i < 256; i += 256) {
        w2ls[i] = w2l[nb * 2 + i];
        w2rs[i] = w2r[nb * 2 + i];
    }

    float acc[4][4][4];
    #pragma unroll
    for (int a = 0; a < 4; a++)
        #pragma unroll
        for (int b = 0; b < 4; b++)
            #pragma unroll
            for (int c = 0; c < 4; c++) acc[a][b][c] = 0.f;

    // ---- tile loader (cp.async) ----
    auto load_stage = [&](int kt, int buf) {
        uint32_t sbuf = sb + buf * STAGE;
        #pragma unroll
        for (int j = 0; j < 2; j++) {
            int cid = tid + 256 * j;          // 0..511
            int r = cid >> 2, u = cid & 3;
            uint32_t so = sbuf + r * ROWB + u * 16;
            size_t arow = rowbase + r;
            int pa = arow < (size_t)N;
            size_t ga = arow * KPAD + kt * BK + u * 8;
            CP16(so,          g_Ahi + ga, pa);
            CP16(so + OFF_AL, g_Alo + ga, pa);
            size_t gb = (size_t)(nb + r) * KPAD + kt * BK + u * 8;
            CP16(so + OFF_BH, g_Bhi + gb, 1);
            CP16(so + OFF_BL, g_Blo + gb, 1);
        }
        CP_COMMIT();
    };

    load_stage(0, 0);

    for (int kt = 0; kt < NITER; kt++) {
        CP_WAIT0();
        __syncthreads();
        if (kt + 1 < NITER) load_stage(kt + 1, (kt + 1) & 1);
        uint32_t sbuf = sb + (kt & 1) * STAGE;

        #pragma unroll
        for (int ks = 0; ks < 2; ks++) {
            // B fragments (hi & lo) for both n16 groups
            uint32_t bh[2][4], bl[2][4];
            #pragma unroll
            for (int nf = 0; nf < 2; nf++) {
                int brow  = wn * 32 + nf * 16 + (lane & 7) + ((lane >> 4) << 3);
                int bunit = ks * 2 + ((lane >> 3) & 1);
                uint32_t ab = sbuf + OFF_BH + brow * ROWB + bunit * 16;
                ldsm4(bh[nf][0], bh[nf][1], bh[nf][2], bh[nf][3], ab);
                ldsm4(bl[nf][0], bl[nf][1], bl[nf][2], bl[nf][3], ab + (OFF_BL - OFF_BH));
            }
            #pragma unroll
            for (int mf = 0; mf < 4; mf++) {
                int arow  = wm * 64 + mf * 16 + (lane & 15);
                int aunit = ks * 2 + (lane >> 4);
                uint32_t aa = sbuf + arow * ROWB + aunit * 16;
                uint32_t ah0, ah1, ah2, ah3, al0, al1, al2, al3;
                ldsm4(ah0, ah1, ah2, ah3, aa);
                ldsm4(al0, al1, al2, al3, aa + OFF_AL);
                #pragma unroll
                for (int nf8 = 0; nf8 < 4; nf8++) {
                    int nf = nf8 >> 1, hf = nf8 & 1;
                    MMA16816(acc[mf][nf8], ah0, ah1, ah2, ah3,
                             bh[nf][hf * 2], bh[nf][hf * 2 + 1]);
                    MMA16816(acc[mf][nf8], ah0, ah1, ah2, ah3,
                             bl[nf][hf * 2], bl[nf][hf * 2 + 1]);
                    MMA16816(acc[mf][nf8], al0, al1, al2, al3,
                             bh[nf][hf * 2], bh[nf][hf * 2 + 1]);
                }
            }
        }
        __syncthreads();
    }

    // ---- fused epilogue: relu(acc+b1) then partial dot with w2l/w2r ----
    float pt0[8], pt1[8], pr0[8], pr1[8];
    #pragma unroll
    for (int i = 0; i < 8; i++) { pt0[i] = pt1[i] = pr0[i] = pr1[i] = 0.f; }

    #pragma unroll
    for (int mf = 0; mf < 4; mf++) {
        #pragma unroll
        for (int nf8 = 0; nf8 < 4; nf8++) {
            #pragma unroll
            for (int j = 0; j < 4; j++) {
                int colL = wn * 32 + nf8 * 8 + 2 * (lane & 3) + (j & 1);
                int i8 = mf * 2 + (j >> 1);
                float h = fmaxf(acc[mf][nf8][j] + b1s[colL], 0.f);
                pt0[i8] += h * w2ls[colL * 2];
                pt1[i8] += h * w2ls[colL * 2 + 1];
                pr0[i8] += h * w2rs[colL * 2];
                pr1[i8] += h * w2rs[colL * 2 + 1];
            }
        }
    }
    #pragma unroll
    for (int i = 0; i < 8; i++) {
        #pragma unroll
        for (int o = 1; o <= 2; o <<= 1) {
            pt0[i] += __shfl_xor_sync(0xffffffffu, pt0[i], o);
            pt1[i] += __shfl_xor_sync(0xffffffffu, pt1[i], o);
            pr0[i] += __shfl_xor_sync(0xffffffffu, pr0[i], o);
            pr1[i] += __shfl_xor_sync(0xffffffffu, pr1[i], o);
        }
        if ((lane & 3) == 0) {
            size_t row = rowbase + wm * 64 + (i >> 1) * 16 + (lane >> 2) + (i & 1) * 8;
            if (row < (size_t)N) {
                asm volatile("red.global.add.v2.f32 [%0], {%1, %2};"
                             :: "l"(&g_t[row * 2]), "f"(pt0[i]), "f"(pt1[i]) : "memory");
                asm volatile("red.global.add.v2.f32 [%0], {%1, %2};"
                             :: "l"(&g_rr[row * 2]), "f"(pr0[i]), "f"(pr1[i]) : "memory");
            }
        }
    }
}

// ---------------- layer-2 scatter + finalize ----------------
__global__ void scatter2_kernel(int E) {
    int e = blockIdx.x * blockDim.x + threadIdx.x;
    if (e >= E) return;
    int s = g_ei[e];
    int d = g_ei[E + e];
    float2 v = *(const float2*)&g_t[s * 2];
    asm volatile("red.global.add.v2.f32 [%0], {%1, %2};"
                 :: "l"(&g_agg2[d * 2]), "f"(v.x), "f"(v.y) : "memory");
}

__global__ void finalize_kernel(float* __restrict__ out, const float* __restrict__ b2, int N) {
    int i = blockIdx.x * blockDim.x + threadIdx.x;
    if (i >= N) return;
    float inv = g_deg[i];
    float2 a = *(const float2*)&g_agg2[2 * i];
    float2 r = *(const float2*)&g_rr[2 * i];
    float2 o;
    o.x = a.x * inv + r.x + __ldg(&b2[0]);
    o.y = a.y * inv + r.y + __ldg(&b2[1]);
    *(float2*)&out[2 * i] = o;
}

// ---------------- edge_index passthrough ----------------
__global__ void ei_out_f32_kernel(float* out, int twoE) {
    int i = blockIdx.x * blockDim.x + threadIdx.x;
    if (i < twoE) out[i] = (float)g_ei[i];
}
__global__ void ei_out_i64_kernel(long long* out, int twoE) {
    int i = blockIdx.x * blockDim.x + threadIdx.x;
    if (i < twoE) out[i] = (long long)g_ei[i];
}

// ---------------- launch ----------------
extern "C" void kernel_launch(void* const* d_in, const int* in_sizes, int n_in,
                              void* d_out, int out_size) {
    const float* x   = (const float*)d_in[0];
    const void*  ei  = d_in[1];
    const float* w1l = (const float*)d_in[2];
    const float* w1r = (const float*)d_in[3];
    const float* b1  = (const float*)d_in[4];
    const float* w2l = (const float*)d_in[5];
    const float* w2r = (const float*)d_in[6];
    const float* b2  = (const float*)d_in[7];

    int N = in_sizes[0] / F_IN_;
    int twoE = in_sizes[1];
    int E = twoE / 2;
    float* out = (float*)d_out;

    static int smem_set = 0;
    if (!smem_set) {
        cudaFuncSetAttribute(gemm_tc_kernel, cudaFuncAttributeMaxDynamicSharedMemorySize,
                             SMEM_DYN);
        smem_set = 1;
    }

    detect_kernel<<<1, 32>>>(ei, twoE);
    convert_ei_kernel<<<1024, 256>>>(ei, twoE);
    zero_all_kernel<<<4096, 256>>>(N);
    scatter1_kernel<<<(E * 32 + 255) / 256, 256>>>(x, E);
    invd_kernel<<<(N + 255) / 256, 256>>>(N);
    prep_A_kernel<<<(N * (KPAD / 8) + 255) / 256, 256>>>(x, N);
    prep_B_kernel<<<(HID_ * (KPAD / 8) + 255) / 256, 256>>>(w1l, w1r);
    dim3 grid((N + 127) / 128, HID_ / 128);
    gemm_tc_kernel<<<grid, 256, SMEM_DYN>>>(b1, w2l, w2r, N);
    scatter2_kernel<<<(E + 255) / 256, 256>>>(E);
    finalize_kernel<<<(N + 255) / 256, 256>>>(out, b2, N);

    long long rem = (long long)out_size - (long long)2 * N;
    if (rem >= (long long)twoE) {
        if (rem >= 2LL * twoE)
            ei_out_i64_kernel<<<(twoE + 255) / 256, 256>>>((long long*)(out + (size_t)2 * N), twoE);
        else
            ei_out_f32_kernel<<<(twoE + 255) / 256, 256>>>(out + (size_t)2 * N, twoE);
    }
}

// round 4
// speedup vs baseline: 3.5328x; 1.1368x over previous
#include <cuda_runtime.h>
#include <cuda_bf16.h>
#include <cstdint>

// ---------------- problem constants ----------------
#define MAXN   200000
#define MAXE   500000
#define F_IN_  165
#define HID_   256
#define KTOT   330
#define APAD   192            // fp32 agg row stride (768B, line-aligned)
#define KPAD   352            // padded K (11 chunks of 32)
#define BK     32
#define NITER  (KPAD / BK)    // 11

// ---------------- device scratch ----------------
__device__ __align__(16) float g_agg[(size_t)MAXN * APAD];   // mean-agg (invd folded)
__device__ float g_deg[MAXN];                                // stores 1/max(deg,1)
__device__ __align__(16) float g_t  [MAXN * 2];
__device__ __align__(16) float g_rr [MAXN * 2];
__device__ __align__(16) __nv_bfloat16 g_Bhi[HID_ * KPAD];
__device__ __align__(16) __nv_bfloat16 g_Blo[HID_ * KPAD];
__device__ int g_ei[2 * MAXE];
__device__ int g_is64;
// CSR build
__device__ int g_cnt[MAXN];
__device__ int g_fc[MAXN];
__device__ int g_rowstart[MAXN + 1];
__device__ int g_blocksum[256];
__device__ int g_csr[MAXE];

// ---------------- PTX helpers (base-ISA; tcgen05 is sm_103a-gated, unusable here) ----------------
__device__ __forceinline__ uint32_t smem_u32(const void* p) {
    uint32_t a;
    asm("{ .reg .u64 t; cvta.to.shared.u64 t, %1; cvt.u32.u64 %0, t; }" : "=r"(a) : "l"(p));
    return a;
}
__device__ __forceinline__ void ldsm4(uint32_t& r0, uint32_t& r1, uint32_t& r2, uint32_t& r3,
                                      uint32_t addr) {
    asm volatile("ldmatrix.sync.aligned.m8n8.x4.shared.b16 {%0,%1,%2,%3}, [%4];"
                 : "=r"(r0), "=r"(r1), "=r"(r2), "=r"(r3) : "r"(addr));
}
#define MMA16816(c, a0, a1, a2, a3, b0, b1)                                            \
    asm volatile(                                                                      \
        "mma.sync.aligned.m16n8k16.row.col.f32.bf16.bf16.f32 "                         \
        "{%0,%1,%2,%3}, {%4,%5,%6,%7}, {%8,%9}, {%0,%1,%2,%3};"                        \
        : "+f"((c)[0]), "+f"((c)[1]), "+f"((c)[2]), "+f"((c)[3])                       \
        : "r"(a0), "r"(a1), "r"(a2), "r"(a3), "r"(b0), "r"(b1))
#define CP16(dst, src, pred)                                                           \
    asm volatile("cp.async.cg.shared.global [%0], [%1], 16, %2;"                       \
                 :: "r"(dst), "l"(src), "r"((pred) ? 16 : 0) : "memory")
#define CP_COMMIT() asm volatile("cp.async.commit_group;" ::: "memory")
#define CP_WAIT(n)  asm volatile("cp.async.wait_group %0;" :: "n"(n) : "memory")

// ---------------- edge index canon ----------------
__global__ void detect_kernel(const void* ei, int twoE) {
    const int* p = (const int*)ei;
    int nz = 0;
    for (int i = threadIdx.x; i < 256; i += 32)
        if (2 * i + 1 < twoE) nz += (p[2 * i + 1] != 0);
    #pragma unroll
    for (int o = 16; o; o >>= 1) nz += __shfl_xor_sync(0xffffffffu, nz, o);
    if (threadIdx.x == 0) g_is64 = (nz == 0) ? 1 : 0;
}
__global__ void convert_ei_kernel(const void* ei, int twoE) {
    int is64 = g_is64;
    const long long* p64 = (const long long*)ei;
    const int* p32 = (const int*)ei;
    for (int i = blockIdx.x * blockDim.x + threadIdx.x; i < twoE; i += gridDim.x * blockDim.x)
        g_ei[i] = is64 ? (int)p64[i] : p32[i];
}

// ---------------- small zero ----------------
__global__ void zero_small_kernel(int N) {
    int i = blockIdx.x * blockDim.x + threadIdx.x;
    if (i < N) { g_cnt[i] = 0; g_fc[i] = 0; }
    if (i < 2 * N) { g_t[i] = 0.f; g_rr[i] = 0.f; }
}

// ---------------- CSR build: hist -> scan -> fill ----------------
__global__ void hist_kernel(int E) {
    int e = blockIdx.x * blockDim.x + threadIdx.x;
    if (e < E) atomicAdd(&g_cnt[g_ei[E + e]], 1);
}

#define SCAN_T 256
#define SCAN_E 1024
__global__ void scan1_kernel(int N) {
    __shared__ int ts[SCAN_T];
    int b = blockIdx.x, t = threadIdx.x;
    int base = b * SCAN_E + t * 4;
    int v[4];
    #pragma unroll
    for (int j = 0; j < 4; j++) v[j] = (base + j < N) ? g_cnt[base + j] : 0;
    int s = v[0] + v[1] + v[2] + v[3];
    ts[t] = s;
    __syncthreads();
    for (int o = 1; o < SCAN_T; o <<= 1) {
        int xv = (t >= o) ? ts[t - o] : 0;
        __syncthreads();
        ts[t] += xv;
        __syncthreads();
    }
    if (t == SCAN_T - 1) g_blocksum[b] = ts[t];
    int run = ts[t] - s;   // exclusive
    #pragma unroll
    for (int j = 0; j < 4; j++) {
        if (base + j < N) g_rowstart[base + j] = run;
        run += v[j];
    }
}
__global__ void scan2_kernel(int nb) {
    __shared__ int ts[256];
    int t = threadIdx.x;
    ts[t] = (t < nb) ? g_blocksum[t] : 0;
    __syncthreads();
    int s = ts[t];
    for (int o = 1; o < 256; o <<= 1) {
        int xv = (t >= o) ? ts[t - o] : 0;
        __syncthreads();
        ts[t] += xv;
        __syncthreads();
    }
    g_blocksum[t] = ts[t] - s;   // exclusive
}
__global__ void scan3_kernel(int N, int E) {
    int i = blockIdx.x * blockDim.x + threadIdx.x;
    if (i < N) g_rowstart[i] += g_blocksum[i / SCAN_E];
    if (i == 0) g_rowstart[N] = E;
}
__global__ void fill_kernel(int E) {
    int e = blockIdx.x * blockDim.x + threadIdx.x;
    if (e >= E) return;
    int s = g_ei[e], d = g_ei[E + e];
    int pos = g_rowstart[d] + atomicAdd(&g_fc[d], 1);
    g_csr[pos] = s;
}

// ---------------- layer-1 aggregation: warp per node, no float atomics ----------------
__global__ void aggregate_kernel(const float* __restrict__ x, int N) {
    int warp = (blockIdx.x * blockDim.x + threadIdx.x) >> 5;
    int lane = threadIdx.x & 31;
    if (warp >= N) return;
    int start = g_rowstart[warp], end = g_rowstart[warp + 1];
    float acc[6] = {0.f, 0.f, 0.f, 0.f, 0.f, 0.f};
    for (int j = start; j < end; j++) {
        int s = g_csr[j];
        const float* xs = x + (size_t)s * F_IN_;
        #pragma unroll
        for (int m = 0; m < 6; m++) {
            int k = lane + 32 * m;
            if (k < F_IN_) acc[m] += xs[k];
        }
    }
    float inv = 1.0f / fmaxf((float)(end - start), 1.0f);
    float* ar = g_agg + (size_t)warp * APAD;
    #pragma unroll
    for (int m = 0; m < 6; m++) {
        int k = lane + 32 * m;
        if (k < F_IN_) ar[k] = acc[m] * inv;
    }
    if (lane == 0) g_deg[warp] = inv;
}

// ---------------- B hi/lo split prep ----------------
__global__ void prep_B_kernel(const float* __restrict__ w1l, const float* __restrict__ w1r) {
    int u = blockIdx.x * blockDim.x + threadIdx.x;
    if (u >= HID_ * (KPAD / 8)) return;
    int n = u / (KPAD / 8);
    int kb = (u % (KPAD / 8)) * 8;
    __align__(16) __nv_bfloat16 hi[8], lo[8];
    #pragma unroll
    for (int j = 0; j < 8; j++) {
        int k = kb + j;
        float v = 0.f;
        if (k < F_IN_)      v = w1l[k * HID_ + n];
        else if (k < KTOT)  v = w1r[(k - F_IN_) * HID_ + n];
        __nv_bfloat16 h = __float2bfloat16(v);
        hi[j] = h;
        lo[j] = __float2bfloat16(v - __bfloat162float(h));
    }
    *(uint4*)(g_Bhi + (size_t)n * KPAD + kb) = *(const uint4*)hi;
    *(uint4*)(g_Blo + (size_t)n * KPAD + kb) = *(const uint4*)lo;
}

// ---------------- mma.sync GEMM (128x256 tile) + in-kernel A split + fused proj2 ----------------
#define ROWB   80
#define SA_SZ  (128 * ROWB)           // 10240
#define SB_SZ  (256 * ROWB)           // 20480
#define OFF_AS(st) ((st) * 2 * SA_SZ)             // [Ahi|Alo] per stage
#define OFF_BS(st) (4 * SA_SZ + (st) * 2 * SB_SZ) // [Bhi|Blo] per stage
#define OFF_TAB    (4 * SA_SZ + 4 * SB_SZ)        // 122880
#define SMEM_DYN   (OFF_TAB + 1024 + 2048 + 2048)

__global__ __launch_bounds__(256, 1) void gemm_tc_kernel(
    const float* __restrict__ x, const float* __restrict__ b1,
    const float* __restrict__ w2l, const float* __restrict__ w2r, int N)
{
    extern __shared__ __align__(16) char sm[];
    uint32_t sb = smem_u32(sm);
    float* b1s  = (float*)(sm + OFF_TAB);
    float* w2ls = (float*)(sm + OFF_TAB + 1024);
    float* w2rs = (float*)(sm + OFF_TAB + 1024 + 2048);

    const int tid  = threadIdx.x;
    const int wid  = tid >> 5;
    const int lane = tid & 31;
    const int wm   = wid >> 2;          // 0..1
    const int wn   = wid & 3;           // 0..3
    const size_t rowbase = (size_t)blockIdx.x * 128;

    for (int i = tid; i < HID_; i += 256) b1s[i] = b1[i];
    for (int i = tid; i < HID_ * 2; i += 256) { w2ls[i] = w2l[i]; w2rs[i] = w2r[i]; }

    float acc[4][8][4];
    #pragma unroll
    for (int a = 0; a < 4; a++)
        #pragma unroll
        for (int b = 0; b < 8; b++)
            #pragma unroll
            for (int c = 0; c < 4; c++) acc[a][b][c] = 0.f;

    // --- A register loader: warp wid handles rows [16*wid, 16*wid+16), lane = k-in-chunk ---
    auto load_A_regs = [&](int kt, float* v) {
        int k = kt * BK + lane;
        int cls = (k < F_IN_) ? 0 : ((k < KTOT) ? 1 : 2);
        #pragma unroll
        for (int r = 0; r < 16; r++) {
            size_t row = rowbase + wid * 16 + r;
            float val = 0.f;
            if (row < (size_t)N) {
                if (cls == 0)      val = g_agg[row * APAD + k];
                else if (cls == 1) val = x[row * F_IN_ + (k - F_IN_)];
            }
            v[r] = val;
        }
    };
    auto store_A = [&](int buf, const float* v) {
        char* basep = sm + OFF_AS(buf);
        #pragma unroll
        for (int r = 0; r < 16; r++) {
            int rl = wid * 16 + r;
            float val = v[r];
            __nv_bfloat16 h = __float2bfloat16(val);
            __nv_bfloat16 l = __float2bfloat16(val - __bfloat162float(h));
            *(__nv_bfloat16*)(basep + rl * ROWB + lane * 2) = h;
            *(__nv_bfloat16*)(basep + SA_SZ + rl * ROWB + lane * 2) = l;
        }
    };
    auto load_B = [&](int kt, int buf) {
        uint32_t sbuf = sb + OFF_BS(buf);
        #pragma unroll
        for (int j = 0; j < 4; j++) {
            int cid = tid + 256 * j;         // 0..1023
            int r = cid >> 2, u = cid & 3;
            uint32_t so = sbuf + r * ROWB + u * 16;
            size_t g = (size_t)r * KPAD + kt * BK + u * 8;
            CP16(so,         g_Bhi + g, 1);
            CP16(so + SB_SZ, g_Blo + g, 1);
        }
        CP_COMMIT();
    };

    float vreg[16];
    load_A_regs(0, vreg);
    load_B(0, 0);

    for (int kt = 0; kt < NITER; kt++) {
        int buf = kt & 1;
        store_A(buf, vreg);
        if (kt + 1 < NITER) {
            load_A_regs(kt + 1, vreg);
            load_B(kt + 1, buf ^ 1);
            CP_WAIT(1);
        } else {
            CP_WAIT(0);
        }
        __syncthreads();

        uint32_t sA = sb + OFF_AS(buf);
        uint32_t sB = sb + OFF_BS(buf);
        #pragma unroll
        for (int ks = 0; ks < 2; ks++) {
            uint32_t bh[4][4], bl[4][4];
            #pragma unroll
            for (int nf = 0; nf < 4; nf++) {
                int brow  = wn * 64 + nf * 16 + (lane & 7) + ((lane >> 4) << 3);
                int bunit = ks * 2 + ((lane >> 3) & 1);
                uint32_t ab = sB + brow * ROWB + bunit * 16;
                ldsm4(bh[nf][0], bh[nf][1], bh[nf][2], bh[nf][3], ab);
                ldsm4(bl[nf][0], bl[nf][1], bl[nf][2], bl[nf][3], ab + SB_SZ);
            }
            #pragma unroll
            for (int mf = 0; mf < 4; mf++) {
                int arow  = wm * 64 + mf * 16 + (lane & 15);
                int aunit = ks * 2 + (lane >> 4);
                uint32_t aa = sA + arow * ROWB + aunit * 16;
                uint32_t ah0, ah1, ah2, ah3, al0, al1, al2, al3;
                ldsm4(ah0, ah1, ah2, ah3, aa);
                ldsm4(al0, al1, al2, al3, aa + SA_SZ);
                #pragma unroll
                for (int nf8 = 0; nf8 < 8; nf8++) {
                    int nf = nf8 >> 1, hf = nf8 & 1;
                    MMA16816(acc[mf][nf8], ah0, ah1, ah2, ah3,
                             bh[nf][hf * 2], bh[nf][hf * 2 + 1]);
                    MMA16816(acc[mf][nf8], ah0, ah1, ah2, ah3,
                             bl[nf][hf * 2], bl[nf][hf * 2 + 1]);
                    MMA16816(acc[mf][nf8], al0, al1, al2, al3,
                             bh[nf][hf * 2], bh[nf][hf * 2 + 1]);
                }
            }
        }
        __syncthreads();
    }

    // ---- fused epilogue: relu(acc+b1) then partial dot with w2l/w2r ----
    float pt0[8], pt1[8], pr0[8], pr1[8];
    #pragma unroll
    for (int i = 0; i < 8; i++) { pt0[i] = pt1[i] = pr0[i] = pr1[i] = 0.f; }

    #pragma unroll
    for (int mf = 0; mf < 4; mf++) {
        #pragma unroll
        for (int nf8 = 0; nf8 < 8; nf8++) {
            #pragma unroll
            for (int j = 0; j < 4; j++) {
                int colL = wn * 64 + nf8 * 8 + 2 * (lane & 3) + (j & 1);
                int i8 = mf * 2 + (j >> 1);
                float h = fmaxf(acc[mf][nf8][j] + b1s[colL], 0.f);
                pt0[i8] += h * w2ls[colL * 2];
                pt1[i8] += h * w2ls[colL * 2 + 1];
                pr0[i8] += h * w2rs[colL * 2];
                pr1[i8] += h * w2rs[colL * 2 + 1];
            }
        }
    }
    #pragma unroll
    for (int i = 0; i < 8; i++) {
        #pragma unroll
        for (int o = 1; o <= 2; o <<= 1) {
            pt0[i] += __shfl_xor_sync(0xffffffffu, pt0[i], o);
            pt1[i] += __shfl_xor_sync(0xffffffffu, pt1[i], o);
            pr0[i] += __shfl_xor_sync(0xffffffffu, pr0[i], o);
            pr1[i] += __shfl_xor_sync(0xffffffffu, pr1[i], o);
        }
        if ((lane & 3) == 0) {
            size_t row = rowbase + wm * 64 + (i >> 1) * 16 + (lane >> 2) + (i & 1) * 8;
            if (row < (size_t)N) {
                asm volatile("red.global.add.v2.f32 [%0], {%1, %2};"
                             :: "l"(&g_t[row * 2]), "f"(pt0[i]), "f"(pt1[i]) : "memory");
                asm volatile("red.global.add.v2.f32 [%0], {%1, %2};"
                             :: "l"(&g_rr[row * 2]), "f"(pr0[i]), "f"(pr1[i]) : "memory");
            }
        }
    }
}

// ---------------- layer-2 gather (CSR) fused with finalize ----------------
__global__ void gather2_kernel(float* __restrict__ out, const float* __restrict__ b2, int N) {
    int warp = (blockIdx.x * blockDim.x + threadIdx.x) >> 5;
    int lane = threadIdx.x & 31;
    if (warp >= N) return;
    int start = g_rowstart[warp], end = g_rowstart[warp + 1];
    float s0 = 0.f, s1 = 0.f;
    for (int j = start + lane; j < end; j += 32) {
        int s = g_csr[j];
        s0 += g_t[s * 2];
        s1 += g_t[s * 2 + 1];
    }
    #pragma unroll
    for (int o = 16; o; o >>= 1) {
        s0 += __shfl_xor_sync(0xffffffffu, s0, o);
        s1 += __shfl_xor_sync(0xffffffffu, s1, o);
    }
    if (lane == 0) {
        float inv = g_deg[warp];
        out[warp * 2]     = s0 * inv + g_rr[warp * 2]     + __ldg(&b2[0]);
        out[warp * 2 + 1] = s1 * inv + g_rr[warp * 2 + 1] + __ldg(&b2[1]);
    }
}

// ---------------- edge_index passthrough ----------------
__global__ void ei_out_f32_kernel(float* out, int twoE) {
    int i = blockIdx.x * blockDim.x + threadIdx.x;
    if (i < twoE) out[i] = (float)g_ei[i];
}
__global__ void ei_out_i64_kernel(long long* out, int twoE) {
    int i = blockIdx.x * blockDim.x + threadIdx.x;
    if (i < twoE) out[i] = (long long)g_ei[i];
}

// ---------------- launch ----------------
extern "C" void kernel_launch(void* const* d_in, const int* in_sizes, int n_in,
                              void* d_out, int out_size) {
    const float* x   = (const float*)d_in[0];
    const void*  ei  = d_in[1];
    const float* w1l = (const float*)d_in[2];
    const float* w1r = (const float*)d_in[3];
    const float* b1  = (const float*)d_in[4];
    const float* w2l = (const float*)d_in[5];
    const float* w2r = (const float*)d_in[6];
    const float* b2  = (const float*)d_in[7];

    int N = in_sizes[0] / F_IN_;
    int twoE = in_sizes[1];
    int E = twoE / 2;
    float* out = (float*)d_out;

    cudaFuncSetAttribute(gemm_tc_kernel, cudaFuncAttributeMaxDynamicSharedMemorySize, SMEM_DYN);

    detect_kernel<<<1, 32>>>(ei, twoE);
    convert_ei_kernel<<<1024, 256>>>(ei, twoE);
    zero_small_kernel<<<(2 * N + 255) / 256, 256>>>(N);
    hist_kernel<<<(E + 255) / 256, 256>>>(E);
    int nsb = (N + SCAN_E - 1) / SCAN_E;
    scan1_kernel<<<nsb, SCAN_T>>>(N);
    scan2_kernel<<<1, 256>>>(nsb);
    scan3_kernel<<<(N + 255) / 256, 256>>>(N, E);
    fill_kernel<<<(E + 255) / 256, 256>>>(E);
    aggregate_kernel<<<(N * 32 + 255) / 256, 256>>>(x, N);
    prep_B_kernel<<<(HID_ * (KPAD / 8) + 255) / 256, 256>>>(w1l, w1r);
    gemm_tc_kernel<<<(N + 127) / 128, 256, SMEM_DYN>>>(x, b1, w2l, w2r, N);
    gather2_kernel<<<(N * 32 + 255) / 256, 256>>>(out, b2, N);

    long long rem = (long long)out_size - (long long)2 * N;
    if (rem >= (long long)twoE) {
        if (rem >= 2LL * twoE)
            ei_out_i64_kernel<<<(twoE + 255) / 256, 256>>>((long long*)(out + (size_t)2 * N), twoE);
        else
            ei_out_f32_kernel<<<(twoE + 255) / 256, 256>>>(out + (size_t)2 * N, twoE);
    }
}